// round 3
// baseline (speedup 1.0000x reference)
#include <cuda_runtime.h>
#include <cstdint>

#define NS    32768
#define NBITS 64
#define MG    8
#define HID   256
#define NC    100

// ---------------------------------------------------------------------------
// Threefry-2x32, 20 rounds — bit-exact match of JAX's threefry2x32 primitive.
// ---------------------------------------------------------------------------
__host__ __device__ __forceinline__ void threefry2x32(
    uint32_t k0, uint32_t k1, uint32_t c0, uint32_t c1,
    uint32_t& o0, uint32_t& o1) {
  uint32_t ks2 = k0 ^ k1 ^ 0x1BD11BDAu;
  uint32_t x0 = c0 + k0;
  uint32_t x1 = c1 + k1;
#define TF_RND(r) { x0 += x1; x1 = (x1 << (r)) | (x1 >> (32 - (r))); x1 ^= x0; }
  TF_RND(13) TF_RND(15) TF_RND(26) TF_RND(6)
  x0 += k1;  x1 += ks2 + 1u;
  TF_RND(17) TF_RND(29) TF_RND(16) TF_RND(24)
  x0 += ks2; x1 += k0 + 2u;
  TF_RND(13) TF_RND(15) TF_RND(26) TF_RND(6)
  x0 += k0;  x1 += k1 + 3u;
  TF_RND(17) TF_RND(29) TF_RND(16) TF_RND(24)
  x0 += k1;  x1 += ks2 + 4u;
  TF_RND(13) TF_RND(15) TF_RND(26) TF_RND(6)
  x0 += ks2; x1 += k0 + 5u;
#undef TF_RND
  o0 = x0; o1 = x1;
}

// ---------------------------------------------------------------------------
// Device-global scratch (no dynamic allocation allowed)
// ---------------------------------------------------------------------------
__device__ float g_xp  [NS * NBITS];   // permuted x
__device__ float g_xmap[NS * NBITS];   // map-flipped permuted x
__device__ unsigned char g_target[NS * MG];
__device__ unsigned int  g_xbits[NS * 2];
__device__ int           g_K[NS];
__device__ unsigned char g_act[NS * NC];
__device__ unsigned char g_ct[NC * MG];
__device__ unsigned int  g_cbits[NC * 2];
__device__ double g_mapSum;
__device__ double g_netSum;
__device__ unsigned long long g_hits;
__device__ unsigned long long g_hamSum;
__device__ unsigned long long g_actTot;
__device__ int g_tmode;   // 0 = 1-byte bool layout, 1 = 4-byte (int32/float32) layout

__device__ __forceinline__ bool read_tpl(const void* p, int b) {
  if (g_tmode == 0) return ((const unsigned char*)p)[b] != 0;
  return ((const int*)p)[b] != 0;
}

// ---------------------------------------------------------------------------
// Kernel 0: zero accumulators + detect template dtype layout.
//  float32 layout: true = 00 00 80 3F  -> byte 0x3F present
//  uint8  layout: nonzero bytes at offsets not divisible by 4 (w.h.p.)
//  int32  layout: nonzero bytes only at 4-aligned offsets, never 0x3F
// ---------------------------------------------------------------------------
__global__ void init_kernel(const unsigned char* tm, const unsigned char* tr) {
  if (threadIdx.x == 0) {
    g_mapSum = 0.0; g_netSum = 0.0;
    g_hits = 0ull; g_hamSum = 0ull; g_actTot = 0ull;
    int has3F = 0, mis = 0;
    for (int i = 0; i < 64; i++) {
      unsigned char bm = tm[i], br = tr[i];
      if (bm == 0x3F || br == 0x3F) has3F = 1;
      if (i & 3) mis += (bm != 0) + (br != 0);
    }
    g_tmode = has3F ? 1 : (mis ? 0 : 1);
  }
}

// ---------------------------------------------------------------------------
// Kernel 1: centroid bit codes (permuted), per-m byte targets
// ---------------------------------------------------------------------------
__global__ void center_kernel(const float* __restrict__ cen,
                              const int* __restrict__ perm) {
  __shared__ int permS[NBITS];
  int t = threadIdx.x;
  if (t < NBITS) permS[t] = perm[t];
  __syncthreads();
  if (t >= NC) return;
  unsigned int w0 = 0, w1 = 0;
  for (int b = 0; b < NBITS; b++) {
    bool bit = cen[t * NBITS + permS[b]] > 0.f;
    if (bit) { if (b < 32) w0 |= 1u << b; else w1 |= 1u << (b - 32); }
  }
  g_cbits[t * 2 + 0] = w0;
  g_cbits[t * 2 + 1] = w1;
  for (int m = 0; m < MG; m++) {
    unsigned int w = (m < 4) ? w0 : w1;
    g_ct[t * MG + m] = (unsigned char)((w >> ((m & 3) * 8)) & 0xffu);
  }
}

// ---------------------------------------------------------------------------
// Kernel 2: PRNG draws, stable argsort ranks of template positions, flips,
// targets, sign bits. 2 rows per 256-thread block; 128 threads/row split as
// 64 (map op) + 64 (raw op).
// ---------------------------------------------------------------------------
__global__ void prep_kernel(const float* __restrict__ x,
                            const int* __restrict__ perm,
                            const void* tmap, const void* traw,
                            uint32_t km0, uint32_t km1,
                            uint32_t kr0, uint32_t kr1) {
  __shared__ float xps[2][NBITS];
  __shared__ unsigned int us[2][2][NBITS];
  __shared__ int permS[NBITS];
  __shared__ int tposS[2][4];
  __shared__ int ranksS[2][2][4];
  __shared__ unsigned int rawb[2][2];
  __shared__ unsigned int xbw[2][2];

  int tid = threadIdx.x;
  if (tid < NBITS) permS[tid] = perm[tid];
  if (tid < 2) {
    const void* tp = (tid == 0) ? tmap : traw;
    int c = 0;
    for (int b = 0; b < NBITS; b++)
      if (read_tpl(tp, b)) { if (c < 4) tposS[tid][c] = b; c++; }
  }
  if (tid < 4) { rawb[tid >> 1][tid & 1] = 0u; xbw[tid >> 1][tid & 1] = 0u; }
  __syncthreads();

  int rid = tid >> 7;
  int sub = tid & 127;
  int op  = sub >> 6;
  int b   = sub & 63;
  int row = blockIdx.x * 2 + rid;

  if (op == 0) xps[rid][b] = x[row * NBITS + permS[b]];
  uint32_t k0 = op ? kr0 : km0;
  uint32_t k1 = op ? kr1 : km1;
  uint32_t o0, o1;
  threefry2x32(k0, k1, 0u, (uint32_t)(row * NBITS + b), o0, o1);
  us[rid][op][b] = (o0 ^ o1) >> 9;   // order-equivalent key of jax uniform
  __syncthreads();

  if (b < 4) {
    int tpos = tposS[op][b];
    unsigned int ut = us[rid][op][tpos];
    int cnt = 0;
    for (int j = 0; j < NBITS; j++) {
      unsigned int uj = us[rid][op][j];
      cnt += (uj < ut) || (uj == ut && j < tpos);
    }
    ranksS[rid][op][b] = cnt;
  }
  __syncthreads();

  float v = xps[rid][b];
  bool flip = (b == ranksS[rid][op][0]) | (b == ranksS[rid][op][1]) |
              (b == ranksS[rid][op][2]) | (b == ranksS[rid][op][3]);
  if (op == 0) {
    g_xp  [row * NBITS + b] = v;
    g_xmap[row * NBITS + b] = flip ? -v : v;
    if (v > 0.f) atomicOr(&xbw[rid][b >> 5], 1u << (b & 31));
  } else {
    bool bit = flip ? (v < 0.f) : (v > 0.f);
    if (bit) atomicOr(&rawb[rid][b >> 5], 1u << (b & 31));
  }
  __syncthreads();

  if (op == 1 && b < MG) {
    unsigned int w = rawb[rid][b >> 2];
    g_target[row * MG + b] = (unsigned char)((w >> ((b & 3) * 8)) & 0xffu);
  }
  if (op == 0 && b < 2) g_xbits[row * 2 + b] = xbw[rid][b];
}

// ---------------------------------------------------------------------------
// Kernel 3: active-class compaction + exact hamming sums. 1 warp / row.
// ---------------------------------------------------------------------------
__global__ void ham_kernel(const int* __restrict__ y) {
  int tid = threadIdx.x, w = tid >> 5, l = tid & 31;
  int row = blockIdx.x * 8 + w;
  unsigned int xb0 = g_xbits[row * 2], xb1 = g_xbits[row * 2 + 1];
  int K = 0;
  unsigned long long hs = 0ull;
  for (int cb = 0; cb < 128; cb += 32) {
    int c = cb + l;
    bool act = (c < NC) && (y[row * NC + c] > 0);
    unsigned int msk = __ballot_sync(0xffffffffu, act);
    if (act) {
      int pos = K + __popc(msk & ((1u << l) - 1u));
      g_act[row * NC + pos] = (unsigned char)c;
      hs += (unsigned long long)(__popc(xb0 ^ g_cbits[c * 2]) +
                                 __popc(xb1 ^ g_cbits[c * 2 + 1]));
    }
    K += __popc(msk);
  }
  if (l == 0) g_K[row] = K;
  for (int o = 16; o; o >>= 1)
    hs += __shfl_xor_sync(0xffffffffu, hs, o);
  if (l == 0) {
    atomicAdd(&g_hamSum, hs);
    atomicAdd(&g_actTot, (unsigned long long)K);
  }
}

// ---------------------------------------------------------------------------
// Kernel 4: fused batched MLP + losses. grid=(512, 2): y=0 map pass, y=1 net.
// CTA: 256 thr, 64 rows, all 256 cols, loop m=0..7.
// warp w owns rows [8w,8w+8); lane l owns cols [8l,8l+8).
// ---------------------------------------------------------------------------
#define SM_XIN   0
#define SM_W1S   4096
#define SM_B1S   6144
#define SM_B2S   6400
#define SM_HBUF  6656            // 64 x 264 (pad 8)
#define SM_W2S   23552           // 32 x 256
#define SM_WRED  31744           // 8 x 256
#define SM_FLOATS 33792          // 135168 bytes

__device__ __forceinline__ float fast_rcp(float d) {
  float r = __uint_as_float(0x7EF311C3u - __float_as_uint(d));
  r = r * (2.0f - d * r);
  r = r * (2.0f - d * r);
  r = r * (2.0f - d * r);
  return r;
}

__global__ void __launch_bounds__(256)
mlp_kernel(const float* __restrict__ W1, const float* __restrict__ b1,
           const float* __restrict__ W2, const float* __restrict__ b2) {
  extern __shared__ float sm[];
  float* xin  = sm + SM_XIN;
  float* W1s  = sm + SM_W1S;
  float* b1s  = sm + SM_B1S;
  float* b2s  = sm + SM_B2S;
  float* hbuf = sm + SM_HBUF;
  float* w2s  = sm + SM_W2S;
  float* wred = sm + SM_WRED;

  int tid = threadIdx.x, w = tid >> 5, l = tid & 31;
  int pass = blockIdx.y;
  int row0 = blockIdx.x * 64;
  const float* inp = (pass == 0) ? g_xmap : g_xp;

  {
    const float4* s4 = (const float4*)(inp + row0 * NBITS);
    float4* d4 = (float4*)xin;
#pragma unroll
    for (int q = 0; q < 4; q++) d4[tid + q * 256] = s4[tid + q * 256];
  }

  double mapAcc = 0.0, netAcc = 0.0;
  unsigned int hitAcc = 0;

  for (int mm = 0; mm < MG; mm++) {
    __syncthreads();
    {
      const float4* w1p = (const float4*)(W1 + mm * 2048);
      float4* w1d = (float4*)W1s;
      w1d[tid] = w1p[tid];
      w1d[tid + 256] = w1p[tid + 256];
      b1s[tid] = b1[mm * 256 + tid];
      b2s[tid] = b2[mm * 256 + tid];
    }
    __syncthreads();

    // ---- GEMM1: h = silu(xs @ W1 + b1), warp-private rows of hbuf ----
#pragma unroll
    for (int kk = 0; kk < 8; kk++) {
      int k = l * 8 + kk;
      float w1c[8];
#pragma unroll
      for (int s = 0; s < 8; s++) w1c[s] = W1s[s * 256 + k];
      float bk = b1s[k];
#pragma unroll
      for (int i = 0; i < 8; i++) {
        const float* xr = xin + (w * 8 + i) * NBITS + mm * 8;
        float a = bk;
#pragma unroll
        for (int s = 0; s < 8; s++) a = fmaf(xr[s], w1c[s], a);
        float t = __expf(-a);
        float d = 1.0f + fminf(t, 1e30f);
        hbuf[(w * 8 + i) * 264 + k] = a * fast_rcp(d);
      }
    }
    __syncwarp();

    // ---- GEMM2: logits = h @ W2, K chunked through smem ----
    float acc[8][8];
#pragma unroll
    for (int i = 0; i < 8; i++)
#pragma unroll
      for (int j = 0; j < 8; j++) acc[i][j] = 0.f;

    const float4* w2g = (const float4*)(W2 + mm * 65536);
    for (int c = 0; c < 8; c++) {
      __syncthreads();
      float4* w2d = (float4*)w2s;
#pragma unroll
      for (int q = 0; q < 8; q++)
        w2d[tid + q * 256] = w2g[c * 2048 + tid + q * 256];
      __syncthreads();

      const float* hb = hbuf + (w * 8) * 264 + c * 32;
#pragma unroll 4
      for (int k = 0; k < 32; k++) {
        float4 wa = *(const float4*)(w2s + k * 256 + l * 8);
        float4 wb = *(const float4*)(w2s + k * 256 + l * 8 + 4);
        float wv0 = wa.x, wv1 = wa.y, wv2 = wa.z, wv3 = wa.w;
        float wv4 = wb.x, wv5 = wb.y, wv6 = wb.z, wv7 = wb.w;
#pragma unroll
        for (int i = 0; i < 8; i++) {
          float hv = hb[i * 264 + k];
          acc[i][0] = fmaf(hv, wv0, acc[i][0]);
          acc[i][1] = fmaf(hv, wv1, acc[i][1]);
          acc[i][2] = fmaf(hv, wv2, acc[i][2]);
          acc[i][3] = fmaf(hv, wv3, acc[i][3]);
          acc[i][4] = fmaf(hv, wv4, acc[i][4]);
          acc[i][5] = fmaf(hv, wv5, acc[i][5]);
          acc[i][6] = fmaf(hv, wv6, acc[i][6]);
          acc[i][7] = fmaf(hv, wv7, acc[i][7]);
        }
      }
    }
#pragma unroll
    for (int i = 0; i < 8; i++)
#pragma unroll
      for (int j = 0; j < 8; j++) acc[i][j] += b2s[l * 8 + j];

    // ---- per-row reductions (warp-level) ----
    float* wr = wred + w * 256;
    for (int i = 0; i < 8; i++) {
      int grow = row0 + w * 8 + i;
      *(float4*)(wr + l * 8)     = make_float4(acc[i][0], acc[i][1], acc[i][2], acc[i][3]);
      *(float4*)(wr + l * 8 + 4) = make_float4(acc[i][4], acc[i][5], acc[i][6], acc[i][7]);

      float mx = acc[i][0]; int ai = l * 8;
#pragma unroll
      for (int j = 1; j < 8; j++)
        if (acc[i][j] > mx) { mx = acc[i][j]; ai = l * 8 + j; }
      for (int o = 16; o; o >>= 1) {
        float vm = __shfl_xor_sync(0xffffffffu, mx, o);
        int   vi = __shfl_xor_sync(0xffffffffu, ai, o);
        if (vm > mx || (vm == mx && vi < ai)) { mx = vm; ai = vi; }
      }
      float se = 0.f;
#pragma unroll
      for (int j = 0; j < 8; j++) se += __expf(acc[i][j] - mx);
      for (int o = 16; o; o >>= 1)
        se += __shfl_xor_sync(0xffffffffu, se, o);
      float lse = mx + __logf(se);
      __syncwarp();

      if (pass == 0) {
        if (l == 0) {
          int tgt = g_target[grow * MG + mm];
          mapAcc += (double)(lse - wr[tgt]);
          hitAcc += (ai == tgt) ? 1u : 0u;
        }
      } else {
        int K = g_K[grow];
        const unsigned char* al = g_act + grow * NC;
        double gs = 0.0;
        for (int ci = l; ci < K; ci += 32)
          gs += (double)wr[g_ct[al[ci] * MG + mm]];
        for (int o = 16; o; o >>= 1)
          gs += __shfl_xor_sync(0xffffffffu, gs, o);
        if (l == 0) netAcc += (double)lse - gs / (double)K;
      }
      __syncwarp();
    }
  }

  if (l == 0) {
    if (pass == 0) {
      atomicAdd(&g_mapSum, mapAcc);
      atomicAdd(&g_hits, (unsigned long long)hitAcc);
    } else {
      atomicAdd(&g_netSum, netAcc);
    }
  }
}

// ---------------------------------------------------------------------------
// Kernel 5: finalize 5 scalars
// ---------------------------------------------------------------------------
__global__ void finalize_kernel(float* out) {
  if (threadIdx.x == 0) {
    double net = g_netSum / (double)NS;
    double map = g_mapSum / (double)NS;
    out[0] = (float)(net + map);
    out[1] = (float)net;
    out[2] = (float)map;
    out[3] = (float)((double)g_hits / ((double)NS * (double)MG));
    out[4] = (float)((double)g_hamSum / (double)g_actTot);
  }
}

// ---------------------------------------------------------------------------
extern "C" void kernel_launch(void* const* d_in, const int* in_sizes, int n_in,
                              void* d_out, int out_size) {
  const float* x    = (const float*)d_in[0];
  const int*   y    = (const int*)  d_in[1];
  const float* cen  = (const float*)d_in[2];
  const int*   perm = (const int*)  d_in[3];
  const void*  tmap = d_in[4];
  const void*  traw = d_in[5];
  const float* W1   = (const float*)d_in[6];
  const float* b1   = (const float*)d_in[7];
  const float* W2   = (const float*)d_in[8];
  const float* b2   = (const float*)d_in[9];
  float* out = (float*)d_out;

  // jax.random.split(jax.random.key(1)) under threefry_partitionable:
  // child i = full output pair of threefry((0,1), hi=0, lo=i)
  uint32_t km0, km1, kr0, kr1;
  threefry2x32(0u, 1u, 0u, 0u, km0, km1);  // template_map flip key
  threefry2x32(0u, 1u, 0u, 1u, kr0, kr1);  // template_raw flip key

  cudaFuncSetAttribute(mlp_kernel, cudaFuncAttributeMaxDynamicSharedMemorySize,
                       SM_FLOATS * 4);

  init_kernel<<<1, 32>>>((const unsigned char*)tmap, (const unsigned char*)traw);
  center_kernel<<<1, 128>>>(cen, perm);
  prep_kernel<<<NS / 2, 256>>>(x, perm, tmap, traw, km0, km1, kr0, kr1);
  ham_kernel<<<NS / 8, 256>>>(y);
  dim3 grid(NS / 64, 2);
  mlp_kernel<<<grid, 256, SM_FLOATS * 4>>>(W1, b1, W2, b2);
  finalize_kernel<<<1, 32>>>(out);
  (void)in_sizes; (void)n_in; (void)out_size;
}

// round 4
// speedup vs baseline: 1.1349x; 1.1349x over previous
#include <cuda_runtime.h>
#include <cstdint>
#include <cstring>

#define NS    32768
#define NBITS 64
#define MG    8
#define HID   256
#define NC    100

typedef unsigned long long ull;

// ---------------------------------------------------------------------------
// Threefry-2x32, 20 rounds — bit-exact match of JAX's threefry2x32 primitive.
// ---------------------------------------------------------------------------
__host__ __device__ __forceinline__ void threefry2x32(
    uint32_t k0, uint32_t k1, uint32_t c0, uint32_t c1,
    uint32_t& o0, uint32_t& o1) {
  uint32_t ks2 = k0 ^ k1 ^ 0x1BD11BDAu;
  uint32_t x0 = c0 + k0;
  uint32_t x1 = c1 + k1;
#define TF_RND(r) { x0 += x1; x1 = (x1 << (r)) | (x1 >> (32 - (r))); x1 ^= x0; }
  TF_RND(13) TF_RND(15) TF_RND(26) TF_RND(6)
  x0 += k1;  x1 += ks2 + 1u;
  TF_RND(17) TF_RND(29) TF_RND(16) TF_RND(24)
  x0 += ks2; x1 += k0 + 2u;
  TF_RND(13) TF_RND(15) TF_RND(26) TF_RND(6)
  x0 += k0;  x1 += k1 + 3u;
  TF_RND(17) TF_RND(29) TF_RND(16) TF_RND(24)
  x0 += k1;  x1 += ks2 + 4u;
  TF_RND(13) TF_RND(15) TF_RND(26) TF_RND(6)
  x0 += ks2; x1 += k0 + 5u;
#undef TF_RND
  o0 = x0; o1 = x1;
}

// ---------------------------------------------------------------------------
// Device-global scratch
// ---------------------------------------------------------------------------
__device__ float g_xp  [NS * NBITS];
__device__ float g_xmap[NS * NBITS];
__device__ unsigned char g_target[NS * MG];
__device__ unsigned int  g_xbits[NS * 2];
__device__ int           g_K[NS];
__device__ unsigned char g_act[NS * NC];
__device__ unsigned char g_ct[NC * MG];
__device__ unsigned int  g_cbits[NC * 2];
__device__ double g_mapSum;
__device__ double g_netSum;
__device__ unsigned long long g_hits;
__device__ unsigned long long g_hamSum;
__device__ unsigned long long g_actTot;
__device__ int g_tmode;

__device__ __forceinline__ bool read_tpl(const void* p, int b) {
  if (g_tmode == 0) return ((const unsigned char*)p)[b] != 0;
  return ((const int*)p)[b] != 0;
}

// ---------------------------------------------------------------------------
// Kernel 0: zero accumulators + detect template dtype layout.
// ---------------------------------------------------------------------------
__global__ void init_kernel(const unsigned char* tm, const unsigned char* tr) {
  if (threadIdx.x == 0) {
    g_mapSum = 0.0; g_netSum = 0.0;
    g_hits = 0ull; g_hamSum = 0ull; g_actTot = 0ull;
    int has3F = 0, mis = 0;
    for (int i = 0; i < 64; i++) {
      unsigned char bm = tm[i], br = tr[i];
      if (bm == 0x3F || br == 0x3F) has3F = 1;
      if (i & 3) mis += (bm != 0) + (br != 0);
    }
    g_tmode = has3F ? 1 : (mis ? 0 : 1);
  }
}

// ---------------------------------------------------------------------------
// Kernel 1: centroid bit codes (permuted), per-m byte targets
// ---------------------------------------------------------------------------
__global__ void center_kernel(const float* __restrict__ cen,
                              const int* __restrict__ perm) {
  __shared__ int permS[NBITS];
  int t = threadIdx.x;
  if (t < NBITS) permS[t] = perm[t];
  __syncthreads();
  if (t >= NC) return;
  unsigned int w0 = 0, w1 = 0;
  for (int b = 0; b < NBITS; b++) {
    bool bit = cen[t * NBITS + permS[b]] > 0.f;
    if (bit) { if (b < 32) w0 |= 1u << b; else w1 |= 1u << (b - 32); }
  }
  g_cbits[t * 2 + 0] = w0;
  g_cbits[t * 2 + 1] = w1;
  for (int m = 0; m < MG; m++) {
    unsigned int w = (m < 4) ? w0 : w1;
    g_ct[t * MG + m] = (unsigned char)((w >> ((m & 3) * 8)) & 0xffu);
  }
}

// ---------------------------------------------------------------------------
// Kernel 2: PRNG draws, stable argsort ranks, flips, targets, sign bits.
// ---------------------------------------------------------------------------
__global__ void prep_kernel(const float* __restrict__ x,
                            const int* __restrict__ perm,
                            const void* tmap, const void* traw,
                            uint32_t km0, uint32_t km1,
                            uint32_t kr0, uint32_t kr1) {
  __shared__ float xps[2][NBITS];
  __shared__ unsigned int us[2][2][NBITS];
  __shared__ int permS[NBITS];
  __shared__ int tposS[2][4];
  __shared__ int ranksS[2][2][4];
  __shared__ unsigned int rawb[2][2];
  __shared__ unsigned int xbw[2][2];

  int tid = threadIdx.x;
  if (tid < NBITS) permS[tid] = perm[tid];
  if (tid < 2) {
    const void* tp = (tid == 0) ? tmap : traw;
    int c = 0;
    for (int b = 0; b < NBITS; b++)
      if (read_tpl(tp, b)) { if (c < 4) tposS[tid][c] = b; c++; }
  }
  if (tid < 4) { rawb[tid >> 1][tid & 1] = 0u; xbw[tid >> 1][tid & 1] = 0u; }
  __syncthreads();

  int rid = tid >> 7;
  int sub = tid & 127;
  int op  = sub >> 6;
  int b   = sub & 63;
  int row = blockIdx.x * 2 + rid;

  if (op == 0) xps[rid][b] = x[row * NBITS + permS[b]];
  uint32_t k0 = op ? kr0 : km0;
  uint32_t k1 = op ? kr1 : km1;
  uint32_t o0, o1;
  threefry2x32(k0, k1, 0u, (uint32_t)(row * NBITS + b), o0, o1);
  us[rid][op][b] = (o0 ^ o1) >> 9;
  __syncthreads();

  if (b < 4) {
    int tpos = tposS[op][b];
    unsigned int ut = us[rid][op][tpos];
    int cnt = 0;
    for (int j = 0; j < NBITS; j++) {
      unsigned int uj = us[rid][op][j];
      cnt += (uj < ut) || (uj == ut && j < tpos);
    }
    ranksS[rid][op][b] = cnt;
  }
  __syncthreads();

  float v = xps[rid][b];
  bool flip = (b == ranksS[rid][op][0]) | (b == ranksS[rid][op][1]) |
              (b == ranksS[rid][op][2]) | (b == ranksS[rid][op][3]);
  if (op == 0) {
    g_xp  [row * NBITS + b] = v;
    g_xmap[row * NBITS + b] = flip ? -v : v;
    if (v > 0.f) atomicOr(&xbw[rid][b >> 5], 1u << (b & 31));
  } else {
    bool bit = flip ? (v < 0.f) : (v > 0.f);
    if (bit) atomicOr(&rawb[rid][b >> 5], 1u << (b & 31));
  }
  __syncthreads();

  if (op == 1 && b < MG) {
    unsigned int w = rawb[rid][b >> 2];
    g_target[row * MG + b] = (unsigned char)((w >> ((b & 3) * 8)) & 0xffu);
  }
  if (op == 0 && b < 2) g_xbits[row * 2 + b] = xbw[rid][b];
}

// ---------------------------------------------------------------------------
// Kernel 3: active-class compaction + exact hamming sums. 1 warp / row.
// ---------------------------------------------------------------------------
__global__ void ham_kernel(const int* __restrict__ y) {
  int tid = threadIdx.x, w = tid >> 5, l = tid & 31;
  int row = blockIdx.x * 8 + w;
  unsigned int xb0 = g_xbits[row * 2], xb1 = g_xbits[row * 2 + 1];
  int K = 0;
  unsigned long long hs = 0ull;
  for (int cb = 0; cb < 128; cb += 32) {
    int c = cb + l;
    bool act = (c < NC) && (y[row * NC + c] > 0);
    unsigned int msk = __ballot_sync(0xffffffffu, act);
    if (act) {
      int pos = K + __popc(msk & ((1u << l) - 1u));
      g_act[row * NC + pos] = (unsigned char)c;
      hs += (unsigned long long)(__popc(xb0 ^ g_cbits[c * 2]) +
                                 __popc(xb1 ^ g_cbits[c * 2 + 1]));
    }
    K += __popc(msk);
  }
  if (l == 0) g_K[row] = K;
  for (int o = 16; o; o >>= 1)
    hs += __shfl_xor_sync(0xffffffffu, hs, o);
  if (l == 0) {
    atomicAdd(&g_hamSum, hs);
    atomicAdd(&g_actTot, (unsigned long long)K);
  }
}

// ---------------------------------------------------------------------------
// Kernel 4: fused batched MLP + losses, FFMA2 (fma.rn.f32x2) version.
//
// CTA: 256 thr = 8 warps; 64 rows; warp w owns rows [8w, 8w+8).
// Lane l owns columns {4l..4l+3} U {128+4l..128+4l+3}  (conflict-free LDS128).
// h stored transposed: float2 slot  k*36 + ((w*4+ip) ^ (k>>3)),
//   pair = (row 2ip, row 2ip+1) of warp w  -> broadcast LDS.64 in GEMM2.
// acc2[ip][j] : f32x2 accumulating rows (2ip, 2ip+1) for column j.
// W2 streamed in 32KB chunks, double-buffered via cp.async.
// ---------------------------------------------------------------------------
#define SM_XIN   0          // 4096  floats
#define SM_W1S   4096       // 2048
#define SM_B1    6144       // 256
#define SM_B2    6400       // 256
#define SM_WRED  6656       // 2048
#define SM_HT    8704       // 18432 (256 k * 36 float2)
#define SM_W2    27136      // 2 * 8192
#define SM_FLOATS 43520     // 174080 bytes

__device__ __forceinline__ void ffma2(ull& d, ull a, ull b) {
  asm("fma.rn.f32x2 %0, %1, %2, %0;" : "+l"(d) : "l"(a), "l"(b));
}
__device__ __forceinline__ ull packdup(float v) {
  ull r;
  asm("mov.b64 %0, {%1, %1};" : "=l"(r) : "f"(v));
  return r;
}
__device__ __forceinline__ float2 unpack2(ull v) {
  float2 t;
  asm("mov.b64 {%0, %1}, %2;" : "=f"(t.x), "=f"(t.y) : "l"(v));
  return t;
}
__device__ __forceinline__ void cpasync16(float* s, const float* g) {
  unsigned sa = (unsigned)__cvta_generic_to_shared(s);
  asm volatile("cp.async.cg.shared.global [%0], [%1], 16;" :: "r"(sa), "l"(g));
}
__device__ __forceinline__ float fast_rcp(float d) {
  float r = __uint_as_float(0x7EF311C3u - __float_as_uint(d));
  r = r * (2.0f - d * r);
  r = r * (2.0f - d * r);
  r = r * (2.0f - d * r);
  return r;
}

__global__ void __launch_bounds__(256)
mlp_kernel(const float* __restrict__ W1, const float* __restrict__ b1,
           const float* __restrict__ W2, const float* __restrict__ b2) {
  extern __shared__ float sm[];
  float* xin  = sm + SM_XIN;
  float* W1s  = sm + SM_W1S;
  float* b1s  = sm + SM_B1;
  float* b2s  = sm + SM_B2;
  float* wred = sm + SM_WRED;
  float* hT   = sm + SM_HT;
  float* w2s  = sm + SM_W2;

  int tid = threadIdx.x, w = tid >> 5, l = tid & 31;
  int pass = blockIdx.y;
  int row0 = blockIdx.x * 64;
  const float* inp = (pass == 0) ? g_xmap : g_xp;

  {
    const float4* s4 = (const float4*)(inp + row0 * NBITS);
    float4* d4 = (float4*)xin;
#pragma unroll
    for (int q = 0; q < 4; q++) d4[tid + q * 256] = s4[tid + q * 256];
  }

  // prefetch global chunk 0 of W2
  {
#pragma unroll
    for (int q = 0; q < 8; q++)
      cpasync16(w2s + (tid + q * 256) * 4, W2 + (tid + q * 256) * 4);
    asm volatile("cp.async.commit_group;");
  }

  double mapAcc = 0.0, netAcc = 0.0;
  unsigned int hitAcc = 0;
  const int w4 = w * 4;

  for (int mm = 0; mm < MG; mm++) {
    __syncthreads();
    {
      const float4* w1p = (const float4*)(W1 + mm * 2048);
      float4* w1d = (float4*)W1s;
      w1d[tid] = w1p[tid];
      w1d[tid + 256] = w1p[tid + 256];
      b1s[tid] = b1[mm * 256 + tid];
      b2s[tid] = b2[mm * 256 + tid];
    }
    __syncthreads();

    // ---- GEMM1: h = silu(xs @ W1 + b1) -> transposed swizzled hT ----
    {
      float xv[8][8];
#pragma unroll
      for (int i = 0; i < 8; i++) {
        float4 a = *(const float4*)(xin + (w * 8 + i) * NBITS + mm * 8);
        float4 bq = *(const float4*)(xin + (w * 8 + i) * NBITS + mm * 8 + 4);
        xv[i][0] = a.x;  xv[i][1] = a.y;  xv[i][2] = a.z;  xv[i][3] = a.w;
        xv[i][4] = bq.x; xv[i][5] = bq.y; xv[i][6] = bq.z; xv[i][7] = bq.w;
      }
#pragma unroll
      for (int kk = 0; kk < 8; kk++) {
        int k = kk * 32 + l;
        float w1c[8];
#pragma unroll
        for (int s = 0; s < 8; s++) w1c[s] = W1s[s * 256 + k];
        float bk = b1s[k];
        float h[8];
#pragma unroll
        for (int i = 0; i < 8; i++) {
          float a = bk;
#pragma unroll
          for (int s = 0; s < 8; s++) a = fmaf(xv[i][s], w1c[s], a);
          float t = __expf(-a);
          float d = 1.0f + fminf(t, 1e30f);
          h[i] = a * fast_rcp(d);
        }
        int ks = k >> 3;
#pragma unroll
        for (int ip = 0; ip < 4; ip++) {
          int slot = k * 36 + ((w4 + ip) ^ ks);
          *(float2*)(hT + slot * 2) = make_float2(h[2 * ip], h[2 * ip + 1]);
        }
      }
    }
    __syncwarp();

    // ---- GEMM2: logits = h @ W2, FFMA2, chunked + double buffered ----
    ull acc2[4][8];
#pragma unroll
    for (int ip = 0; ip < 4; ip++)
#pragma unroll
      for (int j = 0; j < 8; j++) acc2[ip][j] = 0ull;

    for (int c = 0; c < 8; c++) {
      int g = mm * 8 + c;
      if (g + 1 < 64) {
        const float* src = W2 + (g + 1) * 8192;
        float* dst = w2s + ((g + 1) & 1) * 8192;
#pragma unroll
        for (int q = 0; q < 8; q++)
          cpasync16(dst + (tid + q * 256) * 4, src + (tid + q * 256) * 4);
        asm volatile("cp.async.commit_group;");
        asm volatile("cp.async.wait_group 1;");
      } else {
        asm volatile("cp.async.wait_group 0;");
      }
      __syncthreads();

      const float* wch = w2s + (g & 1) * 8192;
      int kbase = c * 32;
#pragma unroll 4
      for (int kk2 = 0; kk2 < 32; kk2++) {
        int k = kbase + kk2;
        float4 wa = *(const float4*)(wch + kk2 * 256 + l * 4);
        float4 wb = *(const float4*)(wch + kk2 * 256 + 128 + l * 4);
        ull wd[8];
        wd[0] = packdup(wa.x); wd[1] = packdup(wa.y);
        wd[2] = packdup(wa.z); wd[3] = packdup(wa.w);
        wd[4] = packdup(wb.x); wd[5] = packdup(wb.y);
        wd[6] = packdup(wb.z); wd[7] = packdup(wb.w);
        int ks = k >> 3;
#pragma unroll
        for (int ip = 0; ip < 4; ip++) {
          int slot = k * 36 + ((w4 + ip) ^ ks);
          ull hv = *(const ull*)(hT + slot * 2);
          ffma2(acc2[ip][0], hv, wd[0]);
          ffma2(acc2[ip][1], hv, wd[1]);
          ffma2(acc2[ip][2], hv, wd[2]);
          ffma2(acc2[ip][3], hv, wd[3]);
          ffma2(acc2[ip][4], hv, wd[4]);
          ffma2(acc2[ip][5], hv, wd[5]);
          ffma2(acc2[ip][6], hv, wd[6]);
          ffma2(acc2[ip][7], hv, wd[7]);
        }
      }
      __syncthreads();
    }

    // ---- per-row reductions (warp-level). lane cols: 4l..4l+3, 128+4l..+3
    float* wr = wred + w * 256;
    for (int i = 0; i < 8; i++) {
      int ip = i >> 1, hf = i & 1;
      int grow = row0 + w * 8 + i;
      float v[8];
#pragma unroll
      for (int j = 0; j < 8; j++) {
        float2 t = unpack2(acc2[ip][j]);
        int col = (j < 4) ? (l * 4 + j) : (128 + l * 4 + (j - 4));
        v[j] = (hf ? t.y : t.x) + b2s[col];
      }
      *(float4*)(wr + l * 4)       = make_float4(v[0], v[1], v[2], v[3]);
      *(float4*)(wr + 128 + l * 4) = make_float4(v[4], v[5], v[6], v[7]);

      float mx = v[0]; int ai = l * 4;
#pragma unroll
      for (int j = 1; j < 8; j++) {
        int col = (j < 4) ? (l * 4 + j) : (128 + l * 4 + (j - 4));
        if (v[j] > mx) { mx = v[j]; ai = col; }
      }
      for (int o = 16; o; o >>= 1) {
        float vm = __shfl_xor_sync(0xffffffffu, mx, o);
        int   vi = __shfl_xor_sync(0xffffffffu, ai, o);
        if (vm > mx || (vm == mx && vi < ai)) { mx = vm; ai = vi; }
      }
      float se = 0.f;
#pragma unroll
      for (int j = 0; j < 8; j++) se += __expf(v[j] - mx);
      for (int o = 16; o; o >>= 1)
        se += __shfl_xor_sync(0xffffffffu, se, o);
      float lse = mx + __logf(se);
      __syncwarp();

      if (pass == 0) {
        if (l == 0) {
          int tgt = g_target[grow * MG + mm];
          mapAcc += (double)(lse - wr[tgt]);
          hitAcc += (ai == tgt) ? 1u : 0u;
        }
      } else {
        int K = g_K[grow];
        const unsigned char* al = g_act + grow * NC;
        double gs = 0.0;
        for (int ci = l; ci < K; ci += 32)
          gs += (double)wr[g_ct[al[ci] * MG + mm]];
        for (int o = 16; o; o >>= 1)
          gs += __shfl_xor_sync(0xffffffffu, gs, o);
        if (l == 0) netAcc += (double)lse - gs / (double)K;
      }
      __syncwarp();
    }
  }

  if (l == 0) {
    if (pass == 0) {
      atomicAdd(&g_mapSum, mapAcc);
      atomicAdd(&g_hits, (unsigned long long)hitAcc);
    } else {
      atomicAdd(&g_netSum, netAcc);
    }
  }
}

// ---------------------------------------------------------------------------
// Kernel 5: finalize 5 scalars
// ---------------------------------------------------------------------------
__global__ void finalize_kernel(float* out) {
  if (threadIdx.x == 0) {
    double net = g_netSum / (double)NS;
    double map = g_mapSum / (double)NS;
    out[0] = (float)(net + map);
    out[1] = (float)net;
    out[2] = (float)map;
    out[3] = (float)((double)g_hits / ((double)NS * (double)MG));
    out[4] = (float)((double)g_hamSum / (double)g_actTot);
  }
}

// ---------------------------------------------------------------------------
extern "C" void kernel_launch(void* const* d_in, const int* in_sizes, int n_in,
                              void* d_out, int out_size) {
  const float* x    = (const float*)d_in[0];
  const int*   y    = (const int*)  d_in[1];
  const float* cen  = (const float*)d_in[2];
  const int*   perm = (const int*)  d_in[3];
  const void*  tmap = d_in[4];
  const void*  traw = d_in[5];
  const float* W1   = (const float*)d_in[6];
  const float* b1   = (const float*)d_in[7];
  const float* W2   = (const float*)d_in[8];
  const float* b2   = (const float*)d_in[9];
  float* out = (float*)d_out;

  uint32_t km0, km1, kr0, kr1;
  threefry2x32(0u, 1u, 0u, 0u, km0, km1);
  threefry2x32(0u, 1u, 0u, 1u, kr0, kr1);

  cudaFuncSetAttribute(mlp_kernel, cudaFuncAttributeMaxDynamicSharedMemorySize,
                       SM_FLOATS * 4);

  init_kernel<<<1, 32>>>((const unsigned char*)tmap, (const unsigned char*)traw);
  center_kernel<<<1, 128>>>(cen, perm);
  prep_kernel<<<NS / 2, 256>>>(x, perm, tmap, traw, km0, km1, kr0, kr1);
  ham_kernel<<<NS / 8, 256>>>(y);
  dim3 grid(NS / 64, 2);
  mlp_kernel<<<grid, 256, SM_FLOATS * 4>>>(W1, b1, W2, b2);
  finalize_kernel<<<1, 32>>>(out);
  (void)in_sizes; (void)n_in; (void)out_size;
}